// round 14
// baseline (speedup 1.0000x reference)
#include <cuda_runtime.h>

#define BDIM 8
#define CDIM 64
#define NDIM 256
#define FDIM 128
#define EPS 1e-5f
#define NCTA (BDIM * CDIM)   // 512

// Scratch (allocation-free rule: __device__ globals)
__device__ unsigned char g_mask[BDIM * CDIM * NDIM];
__device__ float  g_S1[NCTA];
__device__ float  g_S2[NCTA];
__device__ float2 g_wgt[NCTA];       // (w0, w1)
__device__ float2 g_scale[NCTA];     // (w0*gr, w1*gr)
__device__ float  g_shift[NCTA];     // beta - mean*gr
__device__ int    g_done;            // completion counter (self-resetting)

__device__ __forceinline__ float warpsum(float v) {
#pragma unroll
    for (int o = 16; o; o >>= 1) v += __shfl_xor_sync(0xffffffffu, v, o);
    return v;
}

__device__ __forceinline__ float dot4(float4 a, float4 b) {
    return a.x * b.x + a.y * b.y + a.z * b.z + a.w * b.w;
}

// ---------------------------------------------------------------------------
// Kernel 1 (R12-proven): one CTA per (b,c), 256 threads (8 warps),
// 4 rows per warp per iteration, scalarized accumulators, inline epilogue,
// last-CTA stats fold (former k2).
// ---------------------------------------------------------------------------
__global__ void __launch_bounds__(256, 4) k1(const float* __restrict__ h,
                                             const float* __restrict__ op,
                                             const float* __restrict__ opS,
                                             const float* __restrict__ opQ,
                                             const float* __restrict__ gamma,
                                             const float* __restrict__ beta) {
    const int bc  = blockIdx.x;
    const int c   = bc & (CDIM - 1);
    const int tid = threadIdx.x;
    const int w   = tid >> 5, lane = tid & 31;

    const float* hbase = h + (size_t)bc * NDIM * FDIM;
    const float4* op4  = (const float4*)(op  + c * 2 * FDIM);
    const float4* opS4 = (const float4*)(opS + c * 2 * FDIM);
    const float4* opQ4 = (const float4*)(opQ + c * 2 * FDIM);
    const float4 ohi  = op4[32 + lane];   // op[c][128:256] (h part)
    const float4 oSlo = opS4[lane];       // opS[c][0:128]  (mean part)
    const float4 oQlo = opQ4[lane];       // opQ[c][0:128]  (mean part)

    // s_lo = dot(source, op_lo) (source row is L1-hot; once per warp)
    const float4 s0 = ((const float4*)hbase)[lane];
    const float s_lo = warpsum(dot4(s0, op4[lane]));

    __shared__ float accs[7];  // [dS_s, dQ_t, dQ_s, sm_t, sm_s, sq_t, sq_s]
    if (tid < 7) accs[tid] = 0.f;
    __syncthreads();

    float a_dSs = 0.f, a_dQt = 0.f, a_dQs = 0.f;
    float a_smt = 0.f, a_sms = 0.f, a_sqt = 0.f, a_sqs = 0.f;

    // Warp w handles rows n0 = it*32 + w*4 .. +3  (8 iterations)
#pragma unroll 2
    for (int it = 0; it < 8; it++) {
        const int n0 = it * 32 + w * 4;
        const float4* r = (const float4*)(hbase + (size_t)n0 * FDIM);
        const float4 v0 = r[lane];
        const float4 v1 = r[32 + lane];
        const float4 v2 = r[64 + lane];
        const float4 v3 = r[96 + lane];

        float p0 = dot4(v0, ohi);
        float p1 = dot4(v1, ohi);
        float p2 = dot4(v2, ohi);
        float p3 = dot4(v3, ohi);
        // 4 interleaved butterfly chains
#pragma unroll
        for (int o = 16; o; o >>= 1) {
            p0 += __shfl_xor_sync(0xffffffffu, p0, o);
            p1 += __shfl_xor_sync(0xffffffffu, p1, o);
            p2 += __shfl_xor_sync(0xffffffffu, p2, o);
            p3 += __shfl_xor_sync(0xffffffffu, p3, o);
        }
        const float m0 = (s_lo + p0) >= 0.f ? 1.f : 0.f;
        const float m1 = (s_lo + p1) >= 0.f ? 1.f : 0.f;
        const float m2 = (s_lo + p2) >= 0.f ? 1.f : 0.f;
        const float m3 = (s_lo + p3) >= 0.f ? 1.f : 0.f;
        if (lane == 0) {
            uchar4 mk;
            mk.x = (unsigned char)m0; mk.y = (unsigned char)m1;
            mk.z = (unsigned char)m2; mk.w = (unsigned char)m3;
            *(uchar4*)(g_mask + bc * NDIM + n0) = mk;
        }

        // Per-row scalar partials; tot-accums have no mask dependency.
        {
            float pS = dot4(v0, oSlo); a_dSs = fmaf(m0, pS, a_dSs);
            float pQ = dot4(v0, oQlo); a_dQt += pQ; a_dQs = fmaf(m0, pQ, a_dQs);
            float ps = v0.x + v0.y + v0.z + v0.w; a_smt += ps; a_sms = fmaf(m0, ps, a_sms);
            float pq = dot4(v0, v0); a_sqt += pq; a_sqs = fmaf(m0, pq, a_sqs);
        }
        {
            float pS = dot4(v1, oSlo); a_dSs = fmaf(m1, pS, a_dSs);
            float pQ = dot4(v1, oQlo); a_dQt += pQ; a_dQs = fmaf(m1, pQ, a_dQs);
            float ps = v1.x + v1.y + v1.z + v1.w; a_smt += ps; a_sms = fmaf(m1, ps, a_sms);
            float pq = dot4(v1, v1); a_sqt += pq; a_sqs = fmaf(m1, pq, a_sqs);
        }
        {
            float pS = dot4(v2, oSlo); a_dSs = fmaf(m2, pS, a_dSs);
            float pQ = dot4(v2, oQlo); a_dQt += pQ; a_dQs = fmaf(m2, pQ, a_dQs);
            float ps = v2.x + v2.y + v2.z + v2.w; a_smt += ps; a_sms = fmaf(m2, ps, a_sms);
            float pq = dot4(v2, v2); a_sqt += pq; a_sqs = fmaf(m2, pq, a_sqs);
        }
        {
            float pS = dot4(v3, oSlo); a_dSs = fmaf(m3, pS, a_dSs);
            float pQ = dot4(v3, oQlo); a_dQt += pQ; a_dQs = fmaf(m3, pQ, a_dQs);
            float ps = v3.x + v3.y + v3.z + v3.w; a_smt += ps; a_sms = fmaf(m3, ps, a_sms);
            float pq = dot4(v3, v3); a_sqt += pq; a_sqs = fmaf(m3, pq, a_sqs);
        }
    }

    // Fold the 7 per-lane accumulators (interleaved butterflies), then smem.
#pragma unroll
    for (int o = 16; o; o >>= 1) {
        a_dSs += __shfl_xor_sync(0xffffffffu, a_dSs, o);
        a_dQt += __shfl_xor_sync(0xffffffffu, a_dQt, o);
        a_dQs += __shfl_xor_sync(0xffffffffu, a_dQs, o);
        a_smt += __shfl_xor_sync(0xffffffffu, a_smt, o);
        a_sms += __shfl_xor_sync(0xffffffffu, a_sms, o);
        a_sqt += __shfl_xor_sync(0xffffffffu, a_sqt, o);
        a_sqs += __shfl_xor_sync(0xffffffffu, a_sqs, o);
    }
    if (lane == 0) {
        atomicAdd(&accs[0], a_dSs);
        atomicAdd(&accs[1], a_dQt);
        atomicAdd(&accs[2], a_dQs);
        atomicAdd(&accs[3], a_smt);
        atomicAdd(&accs[4], a_sms);
        atomicAdd(&accs[5], a_sqt);
        atomicAdd(&accs[6], a_sqs);
    }
    __syncthreads();

    // Epilogue (warp 0): source dots with opS_hi/opQ_hi, softmax, BN partials
    if (tid < 32) {
        const float4 oShi = opS4[32 + lane];
        const float4 oQhi = opQ4[32 + lane];
        float tSrcS = dot4(s0, oShi);
        float tSrcQ = dot4(s0, oQhi);
#pragma unroll
        for (int o = 16; o; o >>= 1) {
            tSrcS += __shfl_xor_sync(0xffffffffu, tSrcS, o);
            tSrcQ += __shfl_xor_sync(0xffffffffu, tSrcQ, o);
        }
        if (lane == 0) {
            const float tS = accs[0] * (1.f / NDIM) + tSrcS;
            const float tQ = (accs[1] - accs[2]) * (1.f / NDIM) + tSrcQ;
            const float mx = fmaxf(tS, tQ);
            const float e0 = expf(tS - mx), e1 = expf(tQ - mx);
            const float inv = 1.f / (e0 + e1);
            const float w0 = e0 * inv, w1 = e1 * inv;
            g_wgt[bc] = make_float2(w0, w1);
            g_S1[bc] = w0 * accs[4] + w1 * (accs[3] - accs[4]);
            g_S2[bc] = w0 * w0 * accs[6] + w1 * w1 * (accs[5] - accs[6]);
        }
    }
    __syncthreads();

    // ---- Last-CTA stats fold (former k2). Deterministic result regardless
    // of which CTA arrives last; counter self-resets for graph replay. ----
    __shared__ int s_last;
    if (tid == 0) {
        __threadfence();   // publish this CTA's g_S1/g_S2/g_wgt
        s_last = (atomicAdd(&g_done, 1) == NCTA - 1) ? 1 : 0;
    }
    __syncthreads();
    if (s_last) {
        if (tid == 0) g_done = 0;   // reset for next launch/replay
        __threadfence();            // acquire all CTAs' published partials
        __shared__ float2 s_stat[CDIM];
        if (tid < CDIM) {
            float s1 = 0.f, s2 = 0.f;
#pragma unroll
            for (int b = 0; b < BDIM; b++) {
                s1 += g_S1[b * CDIM + tid];
                s2 += g_S2[b * CDIM + tid];
            }
            const float inv = 1.f / (float)(BDIM * NDIM * FDIM);
            const float mean = s1 * inv;
            const float var = s2 * inv - mean * mean;
            s_stat[tid] = make_float2(mean, rsqrtf(var + EPS));
        }
        __syncthreads();
#pragma unroll
        for (int k = 0; k < 2; k++) {
            const int bc2 = tid + k * 256;
            const int c2  = bc2 & (CDIM - 1);
            const float2 st = s_stat[c2];
            const float gr = gamma[c2] * st.y;
            const float2 wv = g_wgt[bc2];
            g_scale[bc2] = make_float2(wv.x * gr, wv.y * gr);
            g_shift[bc2] = beta[c2] - st.x * gr;
        }
    }
}

// ---------------------------------------------------------------------------
// Kernel 3: streaming elementwise, 8 float4 per thread (MLP=8), streaming
// stores (__stcs) so `out` doesn't evict h from L2.
// Block covers 2048 float4, fully inside one (b,c) (4 blocks per bc).
// ---------------------------------------------------------------------------
__global__ __launch_bounds__(256) void k3(const float* __restrict__ h,
                                          float* __restrict__ out) {
    const int tid = threadIdx.x;
    const int i0  = blockIdx.x * 2048 + tid;  // first float4 index
    const int bc  = i0 >> 13;                 // 8192 float4 per (b,c); block spans one bc
    const float2 sc = g_scale[bc];
    const float shift = g_shift[bc];

#pragma unroll
    for (int u = 0; u < 8; u++) {
        const int i = i0 + u * 256;
        const unsigned char m = g_mask[i >> 5];   // uniform per warp (one row per warp)
        const float scale = m ? sc.x : sc.y;
        const float4 hv = ((const float4*)h)[i];
        float4 y;
        y.x = hv.x * scale + shift;
        y.y = hv.y * scale + shift;
        y.z = hv.z * scale + shift;
        y.w = hv.w * scale + shift;
        y.x = (y.x > 0.f) ? y.x : (__expf(y.x) - 1.f);
        y.y = (y.y > 0.f) ? y.y : (__expf(y.y) - 1.f);
        y.z = (y.z > 0.f) ? y.z : (__expf(y.z) - 1.f);
        y.w = (y.w > 0.f) ? y.w : (__expf(y.w) - 1.f);
        __stcs(&((float4*)out)[i], y);
    }
}

extern "C" void kernel_launch(void* const* d_in, const int* in_sizes, int n_in,
                              void* d_out, int out_size) {
    const float* h     = (const float*)d_in[0];
    const float* op    = (const float*)d_in[1];
    const float* opS   = (const float*)d_in[2];
    const float* opQ   = (const float*)d_in[3];
    const float* gamma = (const float*)d_in[4];
    const float* beta  = (const float*)d_in[5];
    float* out = (float*)d_out;

    k1<<<NCTA, 256>>>(h, op, opS, opQ, gamma, beta);
    const int total4 = (BDIM * CDIM * NDIM * FDIM) / 4;  // 4,194,304
    k3<<<total4 / 2048, 256>>>(h, out);
}

// round 15
// speedup vs baseline: 1.0534x; 1.0534x over previous
#include <cuda_runtime.h>

#define BDIM 8
#define CDIM 64
#define NDIM 256
#define FDIM 128
#define EPS 1e-5f
#define NCTA (BDIM * CDIM)   // 512

// Scratch (allocation-free rule: __device__ globals)
__device__ unsigned char g_mask[BDIM * CDIM * NDIM];
__device__ float  g_S1[NCTA];
__device__ float  g_S2[NCTA];
__device__ float2 g_wgt[NCTA];       // (w0, w1)
__device__ float2 g_scale[NCTA];     // (w0*gr, w1*gr)
__device__ float  g_shift[NCTA];     // beta - mean*gr
__device__ int    g_done;            // completion counter (self-resetting)

__device__ __forceinline__ float warpsum(float v) {
#pragma unroll
    for (int o = 16; o; o >>= 1) v += __shfl_xor_sync(0xffffffffu, v, o);
    return v;
}

__device__ __forceinline__ float dot4(float4 a, float4 b) {
    return a.x * b.x + a.y * b.y + a.z * b.z + a.w * b.w;
}

// ---------------------------------------------------------------------------
// Kernel 1 (R12-proven): one CTA per (b,c), 256 threads (8 warps),
// 4 rows per warp per iteration, scalarized accumulators, inline epilogue,
// last-CTA stats fold (former k2).
// ---------------------------------------------------------------------------
__global__ void __launch_bounds__(256, 4) k1(const float* __restrict__ h,
                                             const float* __restrict__ op,
                                             const float* __restrict__ opS,
                                             const float* __restrict__ opQ,
                                             const float* __restrict__ gamma,
                                             const float* __restrict__ beta) {
    const int bc  = blockIdx.x;
    const int c   = bc & (CDIM - 1);
    const int tid = threadIdx.x;
    const int w   = tid >> 5, lane = tid & 31;

    const float* hbase = h + (size_t)bc * NDIM * FDIM;
    const float4* op4  = (const float4*)(op  + c * 2 * FDIM);
    const float4* opS4 = (const float4*)(opS + c * 2 * FDIM);
    const float4* opQ4 = (const float4*)(opQ + c * 2 * FDIM);
    const float4 ohi  = op4[32 + lane];   // op[c][128:256] (h part)
    const float4 oSlo = opS4[lane];       // opS[c][0:128]  (mean part)
    const float4 oQlo = opQ4[lane];       // opQ[c][0:128]  (mean part)

    // s_lo = dot(source, op_lo) (source row is L1-hot; once per warp)
    const float4 s0 = ((const float4*)hbase)[lane];
    const float s_lo = warpsum(dot4(s0, op4[lane]));

    __shared__ float accs[7];  // [dS_s, dQ_t, dQ_s, sm_t, sm_s, sq_t, sq_s]
    if (tid < 7) accs[tid] = 0.f;
    __syncthreads();

    float a_dSs = 0.f, a_dQt = 0.f, a_dQs = 0.f;
    float a_smt = 0.f, a_sms = 0.f, a_sqt = 0.f, a_sqs = 0.f;

    // Warp w handles rows n0 = it*32 + w*4 .. +3  (8 iterations)
#pragma unroll 2
    for (int it = 0; it < 8; it++) {
        const int n0 = it * 32 + w * 4;
        const float4* r = (const float4*)(hbase + (size_t)n0 * FDIM);
        const float4 v0 = r[lane];
        const float4 v1 = r[32 + lane];
        const float4 v2 = r[64 + lane];
        const float4 v3 = r[96 + lane];

        float p0 = dot4(v0, ohi);
        float p1 = dot4(v1, ohi);
        float p2 = dot4(v2, ohi);
        float p3 = dot4(v3, ohi);
        // 4 interleaved butterfly chains
#pragma unroll
        for (int o = 16; o; o >>= 1) {
            p0 += __shfl_xor_sync(0xffffffffu, p0, o);
            p1 += __shfl_xor_sync(0xffffffffu, p1, o);
            p2 += __shfl_xor_sync(0xffffffffu, p2, o);
            p3 += __shfl_xor_sync(0xffffffffu, p3, o);
        }
        const float m0 = (s_lo + p0) >= 0.f ? 1.f : 0.f;
        const float m1 = (s_lo + p1) >= 0.f ? 1.f : 0.f;
        const float m2 = (s_lo + p2) >= 0.f ? 1.f : 0.f;
        const float m3 = (s_lo + p3) >= 0.f ? 1.f : 0.f;
        if (lane == 0) {
            uchar4 mk;
            mk.x = (unsigned char)m0; mk.y = (unsigned char)m1;
            mk.z = (unsigned char)m2; mk.w = (unsigned char)m3;
            *(uchar4*)(g_mask + bc * NDIM + n0) = mk;
        }

        // Per-row scalar partials; tot-accums have no mask dependency.
        {
            float pS = dot4(v0, oSlo); a_dSs = fmaf(m0, pS, a_dSs);
            float pQ = dot4(v0, oQlo); a_dQt += pQ; a_dQs = fmaf(m0, pQ, a_dQs);
            float ps = v0.x + v0.y + v0.z + v0.w; a_smt += ps; a_sms = fmaf(m0, ps, a_sms);
            float pq = dot4(v0, v0); a_sqt += pq; a_sqs = fmaf(m0, pq, a_sqs);
        }
        {
            float pS = dot4(v1, oSlo); a_dSs = fmaf(m1, pS, a_dSs);
            float pQ = dot4(v1, oQlo); a_dQt += pQ; a_dQs = fmaf(m1, pQ, a_dQs);
            float ps = v1.x + v1.y + v1.z + v1.w; a_smt += ps; a_sms = fmaf(m1, ps, a_sms);
            float pq = dot4(v1, v1); a_sqt += pq; a_sqs = fmaf(m1, pq, a_sqs);
        }
        {
            float pS = dot4(v2, oSlo); a_dSs = fmaf(m2, pS, a_dSs);
            float pQ = dot4(v2, oQlo); a_dQt += pQ; a_dQs = fmaf(m2, pQ, a_dQs);
            float ps = v2.x + v2.y + v2.z + v2.w; a_smt += ps; a_sms = fmaf(m2, ps, a_sms);
            float pq = dot4(v2, v2); a_sqt += pq; a_sqs = fmaf(m2, pq, a_sqs);
        }
        {
            float pS = dot4(v3, oSlo); a_dSs = fmaf(m3, pS, a_dSs);
            float pQ = dot4(v3, oQlo); a_dQt += pQ; a_dQs = fmaf(m3, pQ, a_dQs);
            float ps = v3.x + v3.y + v3.z + v3.w; a_smt += ps; a_sms = fmaf(m3, ps, a_sms);
            float pq = dot4(v3, v3); a_sqt += pq; a_sqs = fmaf(m3, pq, a_sqs);
        }
    }

    // Fold the 7 per-lane accumulators (interleaved butterflies), then smem.
#pragma unroll
    for (int o = 16; o; o >>= 1) {
        a_dSs += __shfl_xor_sync(0xffffffffu, a_dSs, o);
        a_dQt += __shfl_xor_sync(0xffffffffu, a_dQt, o);
        a_dQs += __shfl_xor_sync(0xffffffffu, a_dQs, o);
        a_smt += __shfl_xor_sync(0xffffffffu, a_smt, o);
        a_sms += __shfl_xor_sync(0xffffffffu, a_sms, o);
        a_sqt += __shfl_xor_sync(0xffffffffu, a_sqt, o);
        a_sqs += __shfl_xor_sync(0xffffffffu, a_sqs, o);
    }
    if (lane == 0) {
        atomicAdd(&accs[0], a_dSs);
        atomicAdd(&accs[1], a_dQt);
        atomicAdd(&accs[2], a_dQs);
        atomicAdd(&accs[3], a_smt);
        atomicAdd(&accs[4], a_sms);
        atomicAdd(&accs[5], a_sqt);
        atomicAdd(&accs[6], a_sqs);
    }
    __syncthreads();

    // Epilogue (warp 0): source dots with opS_hi/opQ_hi, softmax, BN partials
    if (tid < 32) {
        const float4 oShi = opS4[32 + lane];
        const float4 oQhi = opQ4[32 + lane];
        float tSrcS = dot4(s0, oShi);
        float tSrcQ = dot4(s0, oQhi);
#pragma unroll
        for (int o = 16; o; o >>= 1) {
            tSrcS += __shfl_xor_sync(0xffffffffu, tSrcS, o);
            tSrcQ += __shfl_xor_sync(0xffffffffu, tSrcQ, o);
        }
        if (lane == 0) {
            const float tS = accs[0] * (1.f / NDIM) + tSrcS;
            const float tQ = (accs[1] - accs[2]) * (1.f / NDIM) + tSrcQ;
            const float mx = fmaxf(tS, tQ);
            const float e0 = expf(tS - mx), e1 = expf(tQ - mx);
            const float inv = 1.f / (e0 + e1);
            const float w0 = e0 * inv, w1 = e1 * inv;
            g_wgt[bc] = make_float2(w0, w1);
            g_S1[bc] = w0 * accs[4] + w1 * (accs[3] - accs[4]);
            g_S2[bc] = w0 * w0 * accs[6] + w1 * w1 * (accs[5] - accs[6]);
        }
    }
    __syncthreads();

    // ---- Last-CTA stats fold (former k2). Deterministic result regardless
    // of which CTA arrives last; counter self-resets for graph replay. ----
    __shared__ int s_last;
    if (tid == 0) {
        __threadfence();   // publish this CTA's g_S1/g_S2/g_wgt
        s_last = (atomicAdd(&g_done, 1) == NCTA - 1) ? 1 : 0;
    }
    __syncthreads();
    if (s_last) {
        if (tid == 0) g_done = 0;   // reset for next launch/replay
        __threadfence();            // acquire all CTAs' published partials
        __shared__ float2 s_stat[CDIM];
        if (tid < CDIM) {
            float s1 = 0.f, s2 = 0.f;
#pragma unroll
            for (int b = 0; b < BDIM; b++) {
                s1 += g_S1[b * CDIM + tid];
                s2 += g_S2[b * CDIM + tid];
            }
            const float inv = 1.f / (float)(BDIM * NDIM * FDIM);
            const float mean = s1 * inv;
            const float var = s2 * inv - mean * mean;
            s_stat[tid] = make_float2(mean, rsqrtf(var + EPS));
        }
        __syncthreads();
#pragma unroll
        for (int k = 0; k < 2; k++) {
            const int bc2 = tid + k * 256;
            const int c2  = bc2 & (CDIM - 1);
            const float2 st = s_stat[c2];
            const float gr = gamma[c2] * st.y;
            const float2 wv = g_wgt[bc2];
            g_scale[bc2] = make_float2(wv.x * gr, wv.y * gr);
            g_shift[bc2] = beta[c2] - st.x * gr;
        }
    }
}

// ---------------------------------------------------------------------------
// Kernel 3 (R13-proven shape): streaming elementwise, 4 float4 per thread
// (MLP=4 sweet spot). Cache hints match data lifetimes: __ldlu for h
// (last-use, evict-first) and __stcs for out (streaming, no L2 pollution).
// Block covers 1024 float4, fully inside one (b,c) (8 blocks per bc).
// ---------------------------------------------------------------------------
__global__ __launch_bounds__(256) void k3(const float* __restrict__ h,
                                          float* __restrict__ out) {
    const int tid = threadIdx.x;
    const int i0  = blockIdx.x * 1024 + tid;  // first float4 index
    const int bc  = i0 >> 13;                 // 8192 float4 per (b,c); block spans one bc
    const float2 sc = g_scale[bc];
    const float shift = g_shift[bc];

#pragma unroll
    for (int u = 0; u < 4; u++) {
        const int i = i0 + u * 256;
        const unsigned char m = g_mask[i >> 5];   // uniform per warp (one row per warp)
        const float scale = m ? sc.x : sc.y;
        const float4 hv = __ldlu(&((const float4*)h)[i]);
        float4 y;
        y.x = hv.x * scale + shift;
        y.y = hv.y * scale + shift;
        y.z = hv.z * scale + shift;
        y.w = hv.w * scale + shift;
        y.x = (y.x > 0.f) ? y.x : (__expf(y.x) - 1.f);
        y.y = (y.y > 0.f) ? y.y : (__expf(y.y) - 1.f);
        y.z = (y.z > 0.f) ? y.z : (__expf(y.z) - 1.f);
        y.w = (y.w > 0.f) ? y.w : (__expf(y.w) - 1.f);
        __stcs(&((float4*)out)[i], y);
    }
}

extern "C" void kernel_launch(void* const* d_in, const int* in_sizes, int n_in,
                              void* d_out, int out_size) {
    const float* h     = (const float*)d_in[0];
    const float* op    = (const float*)d_in[1];
    const float* opS   = (const float*)d_in[2];
    const float* opQ   = (const float*)d_in[3];
    const float* gamma = (const float*)d_in[4];
    const float* beta  = (const float*)d_in[5];
    float* out = (float*)d_out;

    k1<<<NCTA, 256>>>(h, op, opS, opQ, gamma, beta);
    const int total4 = (BDIM * CDIM * NDIM * FDIM) / 4;  // 4,194,304
    k3<<<total4 / 1024, 256>>>(h, out);
}

// round 17
// speedup vs baseline: 1.0626x; 1.0087x over previous
#include <cuda_runtime.h>

#define BDIM 8
#define CDIM 64
#define NDIM 256
#define FDIM 128
#define EPS 1e-5f
#define NCTA (BDIM * CDIM)   // 512

// Scratch (allocation-free rule: __device__ globals)
// g_mask layout is PERMUTED: mask of global row n (g=n>>5, j=n&31) lives at
// byte p = (g<<5) | ((j&7)<<2) | (j>>3), so k3's warp wp in block B reads its
// 4 masks (rows B*32+wp+8u, u=0..3) as ONE aligned 4-byte load.
__device__ unsigned char g_mask[BDIM * CDIM * NDIM];
__device__ float  g_S1[NCTA];
__device__ float  g_S2[NCTA];
__device__ float2 g_wgt[NCTA];       // (w0, w1)
__device__ float2 g_scale[NCTA];     // (w0*gr, w1*gr)
__device__ float  g_shift[NCTA];     // beta - mean*gr
__device__ int    g_done;            // completion counter (self-resetting)

__device__ __forceinline__ float warpsum(float v) {
#pragma unroll
    for (int o = 16; o; o >>= 1) v += __shfl_xor_sync(0xffffffffu, v, o);
    return v;
}

__device__ __forceinline__ float dot4(float4 a, float4 b) {
    return a.x * b.x + a.y * b.y + a.z * b.z + a.w * b.w;
}

// ---------------------------------------------------------------------------
// Kernel 1 (R12-proven loop): one CTA per (b,c), 256 threads (8 warps),
// 4 rows per warp per iteration, scalarized accumulators, inline epilogue,
// last-CTA stats fold. Mask stores use the permuted layout (4 byte-stores
// at stride 4 by lane 0 — replaces the old uchar4 store).
// ---------------------------------------------------------------------------
__global__ void __launch_bounds__(256, 4) k1(const float* __restrict__ h,
                                             const float* __restrict__ op,
                                             const float* __restrict__ opS,
                                             const float* __restrict__ opQ,
                                             const float* __restrict__ gamma,
                                             const float* __restrict__ beta) {
    const int bc  = blockIdx.x;
    const int c   = bc & (CDIM - 1);
    const int tid = threadIdx.x;
    const int w   = tid >> 5, lane = tid & 31;

    const float* hbase = h + (size_t)bc * NDIM * FDIM;
    const float4* op4  = (const float4*)(op  + c * 2 * FDIM);
    const float4* opS4 = (const float4*)(opS + c * 2 * FDIM);
    const float4* opQ4 = (const float4*)(opQ + c * 2 * FDIM);
    const float4 ohi  = op4[32 + lane];   // op[c][128:256] (h part)
    const float4 oSlo = opS4[lane];       // opS[c][0:128]  (mean part)
    const float4 oQlo = opQ4[lane];       // opQ[c][0:128]  (mean part)

    // s_lo = dot(source, op_lo) (source row is L1-hot; once per warp)
    const float4 s0 = ((const float4*)hbase)[lane];
    const float s_lo = warpsum(dot4(s0, op4[lane]));

    __shared__ float accs[7];  // [dS_s, dQ_t, dQ_s, sm_t, sm_s, sq_t, sq_s]
    if (tid < 7) accs[tid] = 0.f;
    __syncthreads();

    float a_dSs = 0.f, a_dQt = 0.f, a_dQs = 0.f;
    float a_smt = 0.f, a_sms = 0.f, a_sqt = 0.f, a_sqs = 0.f;

    // Warp w handles rows n0 = it*32 + w*4 .. +3  (8 iterations)
#pragma unroll 2
    for (int it = 0; it < 8; it++) {
        const int n0 = it * 32 + w * 4;
        const float4* r = (const float4*)(hbase + (size_t)n0 * FDIM);
        const float4 v0 = r[lane];
        const float4 v1 = r[32 + lane];
        const float4 v2 = r[64 + lane];
        const float4 v3 = r[96 + lane];

        float p0 = dot4(v0, ohi);
        float p1 = dot4(v1, ohi);
        float p2 = dot4(v2, ohi);
        float p3 = dot4(v3, ohi);
        // 4 interleaved butterfly chains
#pragma unroll
        for (int o = 16; o; o >>= 1) {
            p0 += __shfl_xor_sync(0xffffffffu, p0, o);
            p1 += __shfl_xor_sync(0xffffffffu, p1, o);
            p2 += __shfl_xor_sync(0xffffffffu, p2, o);
            p3 += __shfl_xor_sync(0xffffffffu, p3, o);
        }
        const float m0 = (s_lo + p0) >= 0.f ? 1.f : 0.f;
        const float m1 = (s_lo + p1) >= 0.f ? 1.f : 0.f;
        const float m2 = (s_lo + p2) >= 0.f ? 1.f : 0.f;
        const float m3 = (s_lo + p3) >= 0.f ? 1.f : 0.f;
        if (lane == 0) {
            // Permuted mask store: granule g = bc*8 + it, j = w*4 + k.
            const int gb = (bc * 8 + it) << 5;
            const unsigned char mv0 = (unsigned char)m0;
            const unsigned char mv1 = (unsigned char)m1;
            const unsigned char mv2 = (unsigned char)m2;
            const unsigned char mv3 = (unsigned char)m3;
            const int j0 = w * 4;
            g_mask[gb | (((j0 + 0) & 7) << 2) | ((j0 + 0) >> 3)] = mv0;
            g_mask[gb | (((j0 + 1) & 7) << 2) | ((j0 + 1) >> 3)] = mv1;
            g_mask[gb | (((j0 + 2) & 7) << 2) | ((j0 + 2) >> 3)] = mv2;
            g_mask[gb | (((j0 + 3) & 7) << 2) | ((j0 + 3) >> 3)] = mv3;
        }

        // Per-row scalar partials; tot-accums have no mask dependency.
        {
            float pS = dot4(v0, oSlo); a_dSs = fmaf(m0, pS, a_dSs);
            float pQ = dot4(v0, oQlo); a_dQt += pQ; a_dQs = fmaf(m0, pQ, a_dQs);
            float ps = v0.x + v0.y + v0.z + v0.w; a_smt += ps; a_sms = fmaf(m0, ps, a_sms);
            float pq = dot4(v0, v0); a_sqt += pq; a_sqs = fmaf(m0, pq, a_sqs);
        }
        {
            float pS = dot4(v1, oSlo); a_dSs = fmaf(m1, pS, a_dSs);
            float pQ = dot4(v1, oQlo); a_dQt += pQ; a_dQs = fmaf(m1, pQ, a_dQs);
            float ps = v1.x + v1.y + v1.z + v1.w; a_smt += ps; a_sms = fmaf(m1, ps, a_sms);
            float pq = dot4(v1, v1); a_sqt += pq; a_sqs = fmaf(m1, pq, a_sqs);
        }
        {
            float pS = dot4(v2, oSlo); a_dSs = fmaf(m2, pS, a_dSs);
            float pQ = dot4(v2, oQlo); a_dQt += pQ; a_dQs = fmaf(m2, pQ, a_dQs);
            float ps = v2.x + v2.y + v2.z + v2.w; a_smt += ps; a_sms = fmaf(m2, ps, a_sms);
            float pq = dot4(v2, v2); a_sqt += pq; a_sqs = fmaf(m2, pq, a_sqs);
        }
        {
            float pS = dot4(v3, oSlo); a_dSs = fmaf(m3, pS, a_dSs);
            float pQ = dot4(v3, oQlo); a_dQt += pQ; a_dQs = fmaf(m3, pQ, a_dQs);
            float ps = v3.x + v3.y + v3.z + v3.w; a_smt += ps; a_sms = fmaf(m3, ps, a_sms);
            float pq = dot4(v3, v3); a_sqt += pq; a_sqs = fmaf(m3, pq, a_sqs);
        }
    }

    // Fold the 7 per-lane accumulators (interleaved butterflies), then smem.
#pragma unroll
    for (int o = 16; o; o >>= 1) {
        a_dSs += __shfl_xor_sync(0xffffffffu, a_dSs, o);
        a_dQt += __shfl_xor_sync(0xffffffffu, a_dQt, o);
        a_dQs += __shfl_xor_sync(0xffffffffu, a_dQs, o);
        a_smt += __shfl_xor_sync(0xffffffffu, a_smt, o);
        a_sms += __shfl_xor_sync(0xffffffffu, a_sms, o);
        a_sqt += __shfl_xor_sync(0xffffffffu, a_sqt, o);
        a_sqs += __shfl_xor_sync(0xffffffffu, a_sqs, o);
    }
    if (lane == 0) {
        atomicAdd(&accs[0], a_dSs);
        atomicAdd(&accs[1], a_dQt);
        atomicAdd(&accs[2], a_dQs);
        atomicAdd(&accs[3], a_smt);
        atomicAdd(&accs[4], a_sms);
        atomicAdd(&accs[5], a_sqt);
        atomicAdd(&accs[6], a_sqs);
    }
    __syncthreads();

    // Epilogue (warp 0): source dots with opS_hi/opQ_hi, softmax, BN partials
    if (tid < 32) {
        const float4 oShi = opS4[32 + lane];
        const float4 oQhi = opQ4[32 + lane];
        float tSrcS = dot4(s0, oShi);
        float tSrcQ = dot4(s0, oQhi);
#pragma unroll
        for (int o = 16; o; o >>= 1) {
            tSrcS += __shfl_xor_sync(0xffffffffu, tSrcS, o);
            tSrcQ += __shfl_xor_sync(0xffffffffu, tSrcQ, o);
        }
        if (lane == 0) {
            const float tS = accs[0] * (1.f / NDIM) + tSrcS;
            const float tQ = (accs[1] - accs[2]) * (1.f / NDIM) + tSrcQ;
            const float mx = fmaxf(tS, tQ);
            const float e0 = expf(tS - mx), e1 = expf(tQ - mx);
            const float inv = 1.f / (e0 + e1);
            const float w0 = e0 * inv, w1 = e1 * inv;
            g_wgt[bc] = make_float2(w0, w1);
            g_S1[bc] = w0 * accs[4] + w1 * (accs[3] - accs[4]);
            g_S2[bc] = w0 * w0 * accs[6] + w1 * w1 * (accs[5] - accs[6]);
        }
    }
    __syncthreads();

    // ---- Last-CTA stats fold (former k2). Deterministic result regardless
    // of which CTA arrives last; counter self-resets for graph replay. ----
    __shared__ int s_last;
    if (tid == 0) {
        __threadfence();   // publish this CTA's g_S1/g_S2/g_wgt
        s_last = (atomicAdd(&g_done, 1) == NCTA - 1) ? 1 : 0;
    }
    __syncthreads();
    if (s_last) {
        if (tid == 0) g_done = 0;   // reset for next launch/replay
        __threadfence();            // acquire all CTAs' published partials
        __shared__ float2 s_stat[CDIM];
        if (tid < CDIM) {
            float s1 = 0.f, s2 = 0.f;
#pragma unroll
            for (int b = 0; b < BDIM; b++) {
                s1 += g_S1[b * CDIM + tid];
                s2 += g_S2[b * CDIM + tid];
            }
            const float inv = 1.f / (float)(BDIM * NDIM * FDIM);
            const float mean = s1 * inv;
            const float var = s2 * inv - mean * mean;
            s_stat[tid] = make_float2(mean, rsqrtf(var + EPS));
        }
        __syncthreads();
#pragma unroll
        for (int k = 0; k < 2; k++) {
            const int bc2 = tid + k * 256;
            const int c2  = bc2 & (CDIM - 1);
            const float2 st = s_stat[c2];
            const float gr = gamma[c2] * st.y;
            const float2 wv = g_wgt[bc2];
            g_scale[bc2] = make_float2(wv.x * gr, wv.y * gr);
            g_shift[bc2] = beta[c2] - st.x * gr;
        }
    }
}

// ---------------------------------------------------------------------------
// Kernel 3 (R15-proven shape): streaming elementwise, 4 float4 per thread,
// __ldlu for h (last-use), __stcs for out (streaming). NEW: one aligned
// 4-byte mask load per warp (permuted g_mask layout), bytes extracted by
// shift — removes 3 LDGs/thread and the per-iteration mask dependency.
// Block covers 1024 float4, fully inside one (b,c) (8 blocks per bc).
// ---------------------------------------------------------------------------
__global__ __launch_bounds__(256) void k3(const float* __restrict__ h,
                                          float* __restrict__ out) {
    const int tid = threadIdx.x;
    const int wp  = tid >> 5;
    const int i0  = blockIdx.x * 1024 + tid;  // first float4 index
    const int bc  = i0 >> 13;                 // 8192 float4 per (b,c); block spans one bc
    const float2 sc = g_scale[bc];
    const float shift = g_shift[bc];

    // One 4-byte broadcast load: masks for this warp's 4 rows (u=0..3).
    const unsigned int mw =
        *(const unsigned int*)(g_mask + (blockIdx.x << 5) + (wp << 2));

#pragma unroll
    for (int u = 0; u < 4; u++) {
        const int i = i0 + u * 256;
        const float scale = ((mw >> (8 * u)) & 1u) ? sc.x : sc.y;
        const float4 hv = __ldlu(&((const float4*)h)[i]);
        float4 y;
        y.x = hv.x * scale + shift;
        y.y = hv.y * scale + shift;
        y.z = hv.z * scale + shift;
        y.w = hv.w * scale + shift;
        y.x = (y.x > 0.f) ? y.x : (__expf(y.x) - 1.f);
        y.y = (y.y > 0.f) ? y.y : (__expf(y.y) - 1.f);
        y.z = (y.z > 0.f) ? y.z : (__expf(y.z) - 1.f);
        y.w = (y.w > 0.f) ? y.w : (__expf(y.w) - 1.f);
        __stcs(&((float4*)out)[i], y);
    }
}

extern "C" void kernel_launch(void* const* d_in, const int* in_sizes, int n_in,
                              void* d_out, int out_size) {
    const float* h     = (const float*)d_in[0];
    const float* op    = (const float*)d_in[1];
    const float* opS   = (const float*)d_in[2];
    const float* opQ   = (const float*)d_in[3];
    const float* gamma = (const float*)d_in[4];
    const float* beta  = (const float*)d_in[5];
    float* out = (float*)d_out;

    k1<<<NCTA, 256>>>(h, op, opS, opQ, gamma, beta);
    const int total4 = (BDIM * CDIM * NDIM * FDIM) / 4;  // 4,194,304
    k3<<<total4 / 1024, 256>>>(h, out);
}